// round 10
// baseline (speedup 1.0000x reference)
#include <cuda_runtime.h>
#include <cuda_fp16.h>
#include <math.h>
#include <cstdint>

#define T_LEN 512
#define BSZ   256
#define DIM   512
#define HID   512
#define N4    (4 * HID)       /* 2048 */

// Scratch: input projections [T][B][4H].
__device__ float g_Y[268435456];          // 131072 * 2048
// fp16 copies of X and W (W rows: gate*512 + r, gates f,i,o,a).
__device__ __half g_Xf[67108864];         // 131072 * 512
__device__ __half g_Wf[1048576];          // 2048 * 512
// Double-buffered fp16 h state [2][256][512].
__device__ __half g_h16[262144];

// ============================================================================
// helpers
// ============================================================================
__device__ __forceinline__ uint32_t smem_u32(const void* p) {
    uint32_t a;
    asm("{ .reg .u64 t; cvta.to.shared.u64 t, %1; cvt.u32.u64 %0, t; }"
        : "=r"(a) : "l"(p));
    return a;
}
__device__ __forceinline__ void ldsm_x4(uint32_t& r0, uint32_t& r1,
                                        uint32_t& r2, uint32_t& r3,
                                        uint32_t addr) {
    asm volatile("ldmatrix.sync.aligned.m8n8.x4.shared.b16 {%0,%1,%2,%3}, [%4];"
                 : "=r"(r0), "=r"(r1), "=r"(r2), "=r"(r3) : "r"(addr));
}
__device__ __forceinline__ void mma16816(float* c, const uint32_t* a,
                                         uint32_t b0, uint32_t b1) {
    asm volatile(
        "mma.sync.aligned.m16n8k16.row.col.f32.f16.f16.f32 "
        "{%0,%1,%2,%3}, {%4,%5,%6,%7}, {%8,%9}, {%0,%1,%2,%3};"
        : "+f"(c[0]), "+f"(c[1]), "+f"(c[2]), "+f"(c[3])
        : "r"(a[0]), "r"(a[1]), "r"(a[2]), "r"(a[3]), "r"(b0), "r"(b1));
}
#define CP_ASYNC16(dst, src) \
    asm volatile("cp.async.cg.shared.global [%0], [%1], 16;" \
                 :: "r"(dst), "l"(src) : "memory")
#define CP_COMMIT() asm volatile("cp.async.commit_group;" ::: "memory")
#define CP_WAIT(n)  asm volatile("cp.async.wait_group %0;" :: "n"(n) : "memory")
#define CLUSTER_ARRIVE() \
    asm volatile("barrier.cluster.arrive.aligned;" ::: "memory")
#define CLUSTER_WAIT() \
    asm volatile("barrier.cluster.wait.aligned;" ::: "memory")

// ============================================================================
// One-time fp32 -> fp16 conversion kernels.
// ============================================================================
__global__ __launch_bounds__(256) void convert_x_h(const float* __restrict__ X) {
    size_t i = (size_t)blockIdx.x * blockDim.x + threadIdx.x;   // per float4
    float4 v = reinterpret_cast<const float4*>(X)[i];
    __half2 a = __floats2half2_rn(v.x, v.y);
    __half2 b = __floats2half2_rn(v.z, v.w);
    reinterpret_cast<uint2*>(g_Xf)[i] =
        make_uint2(*reinterpret_cast<uint32_t*>(&a),
                   *reinterpret_cast<uint32_t*>(&b));
}
__global__ __launch_bounds__(256) void convert_w_h(
    const float* __restrict__ Wf, const float* __restrict__ Wi,
    const float* __restrict__ Wo, const float* __restrict__ Wa) {
    size_t i = (size_t)blockIdx.x * blockDim.x + threadIdx.x;   // per float4
    int gate = (int)(i >> 16);                  // 65536 float4 per gate
    const float* W = (gate == 0) ? Wf : (gate == 1) ? Wi : (gate == 2) ? Wo : Wa;
    float4 v = reinterpret_cast<const float4*>(W)[i & 65535];
    __half2 a = __floats2half2_rn(v.x, v.y);
    __half2 b = __floats2half2_rn(v.z, v.w);
    reinterpret_cast<uint2*>(g_Wf)[i] =
        make_uint2(*reinterpret_cast<uint32_t*>(&a),
                   *reinterpret_cast<uint32_t*>(&b));
}

// ============================================================================
// GEMM1 via fp16 mma.sync (1 term, fp32 acc), cp.async 2-stage pipeline.
// (round-8 version, verbatim)
// ============================================================================
__global__ __launch_bounds__(256, 2) void gemm_xproj_mma(
    const float* __restrict__ bf, const float* __restrict__ bi,
    const float* __restrict__ bo)
{
    extern __shared__ __align__(128) char smem[];
    const uint32_t sb = smem_u32(smem);

    const int tid  = threadIdx.x;
    const int lane = tid & 31;
    const int wid  = tid >> 5;
    const int wm   = wid >> 1;
    const int wn   = wid & 1;

    const int nTile = blockIdx.x;
    const int mBase = blockIdx.y * 128;
    const int gate  = nTile >> 2;
    const int rowG  = (nTile & 3) * 128;
    const float* bias = (gate == 0) ? bf : (gate == 1) ? bi : (gate == 2) ? bo : nullptr;

    const __half* A = g_Xf + (size_t)mBase * DIM;
    const __half* B = g_Wf + (size_t)nTile * 128 * DIM;

    float c[2][8][4];
#pragma unroll
    for (int mf = 0; mf < 2; mf++)
#pragma unroll
        for (int nf = 0; nf < 8; nf++)
#pragma unroll
            for (int q = 0; q < 4; q++) c[mf][nf][q] = 0.f;

    auto stage = [&](int chunk, int s) {
        const int kb = chunk * 64;
        const uint32_t sOff = (uint32_t)s * 32768;
#pragma unroll
        for (int it = 0; it < 4; it++) {
            int idx = tid + it * 256;
            int row = idx >> 3;
            int ch  = idx & 7;
            uint32_t off = sOff + (uint32_t)row * 128 + ((ch ^ (row & 7)) << 4);
            const size_t g = (size_t)row * DIM + kb + ch * 8;
            CP_ASYNC16(sb + off,         A + g);
            CP_ASYNC16(sb + off + 16384, B + g);
        }
        CP_COMMIT();
    };

    stage(0, 0);

    for (int chunk = 0; chunk < 8; chunk++) {
        if (chunk < 7) {
            stage(chunk + 1, (chunk + 1) & 1);
            CP_WAIT(1);
        } else {
            CP_WAIT(0);
        }
        __syncthreads();

        const uint32_t sOff = (uint32_t)(chunk & 1) * 32768;
        const uint32_t AS = sOff, BS = sOff + 16384;

#pragma unroll
        for (int ks = 0; ks < 4; ks++) {
            const int chv = ks * 2 + (lane >> 4);

            uint32_t a[2][4];
#pragma unroll
            for (int mf = 0; mf < 2; mf++) {
                const int row = wm * 32 + mf * 16 + (lane & 15);
                const uint32_t addr =
                    sb + AS + (uint32_t)row * 128 + (((chv ^ (row & 7))) << 4);
                ldsm_x4(a[mf][0], a[mf][1], a[mf][2], a[mf][3], addr);
            }
            uint32_t b[4][4];
#pragma unroll
            for (int np = 0; np < 4; np++) {
                const int row = wn * 64 + np * 16 + (lane & 15);
                const uint32_t addr =
                    sb + BS + (uint32_t)row * 128 + (((chv ^ (row & 7))) << 4);
                ldsm_x4(b[np][0], b[np][1], b[np][2], b[np][3], addr);
            }
#pragma unroll
            for (int mf = 0; mf < 2; mf++)
#pragma unroll
                for (int nf = 0; nf < 8; nf++) {
                    const int np = nf >> 1, s = nf & 1;
                    mma16816(c[mf][nf], a[mf], b[np][s], b[np][s + 2]);
                }
        }
        __syncthreads();
    }

    const int colBase = nTile * 128 + wn * 64 + (lane & 3) * 2;
    const int rBase   = mBase + wm * 32 + (lane >> 2);
#pragma unroll
    for (int nf = 0; nf < 8; nf++) {
        const int col = colBase + nf * 8;
        const int ln  = wn * 64 + nf * 8 + (lane & 3) * 2;
        float b0 = bias ? __ldg(bias + rowG + ln)     : 0.f;
        float b1 = bias ? __ldg(bias + rowG + ln + 1) : 0.f;
#pragma unroll
        for (int mf = 0; mf < 2; mf++) {
            const size_t r0 = (size_t)(rBase + mf * 16);
            float2 o0 = make_float2(c[mf][nf][0] + b0, c[mf][nf][1] + b1);
            float2 o1 = make_float2(c[mf][nf][2] + b0, c[mf][nf][3] + b1);
            *reinterpret_cast<float2*>(g_Y + r0 * N4 + col)       = o0;
            *reinterpret_cast<float2*>(g_Y + (r0 + 8) * N4 + col) = o1;
        }
    }
}

// ============================================================================
// Persistent tensor-core recurrence, 8-CTA clusters.
// 128 blocks = 16 clusters (mTile, 16 rows) x 8 ranks (nTile, 64 cols).
// Warp tile 16m x 8n, K=512 in k32 steps, W_aa as fp16 hi/lo (2-term),
// 4 independent accumulator chains. h exchanged via g_h16 (double-buffered);
// sync via barrier.cluster (cluster-scope release/acquire).
// ============================================================================
__device__ __forceinline__ float sigf(float x) {
    return 1.f / (1.f + __expf(-x));
}
__device__ __forceinline__ float tanh_fast(float x) {
    return 2.f / (1.f + __expf(-2.f * x)) - 1.f;
}

__global__ __launch_bounds__(256, 1) __cluster_dims__(8, 1, 1)
void lstm_persistent_tc(
    const float* __restrict__ Waa,
    const float* __restrict__ ba,
    float*       __restrict__ out,
    float*       __restrict__ hn)
{
    extern __shared__ __align__(128) char sm[];
    const uint32_t sb   = smem_u32(sm);
    const uint32_t sbWh = sb;
    const uint32_t sbWl = sb + 65536;
    const uint32_t sbH  = sb + 131072;

    const int tid  = threadIdx.x;
    const int lane = tid & 31;
    const int wid  = tid >> 5;                 // 0..7: n-subtile
    const int m0 = (blockIdx.x >> 3) * 16;     // cluster id = mTile
    const int n0 = (blockIdx.x & 7) * 64;      // cluster rank = nTile

    // --- one-time: Waa[n0+n][k] -> smem hi/lo fp16, swizzled 16B chunks ---
#pragma unroll
    for (int i = 0; i < 16; i++) {
        int idx = tid + i * 256;          // n(0..63) x chunk(0..63)
        int n = idx >> 6;
        int c = idx & 63;
        const float* src = Waa + (size_t)(n0 + n) * HID + c * 8;
        float4 v0 = *reinterpret_cast<const float4*>(src);
        float4 v1 = *reinterpret_cast<const float4*>(src + 4);
        float xs[8] = {v0.x, v0.y, v0.z, v0.w, v1.x, v1.y, v1.z, v1.w};
        __half2 hh[4], ll[4];
#pragma unroll
        for (int q = 0; q < 4; q++) {
            __half h0 = __float2half_rn(xs[q * 2]);
            __half h1 = __float2half_rn(xs[q * 2 + 1]);
            __half l0 = __float2half_rn(xs[q * 2]     - __half2float(h0));
            __half l1 = __float2half_rn(xs[q * 2 + 1] - __half2float(h1));
            hh[q] = __halves2half2(h0, h1);
            ll[q] = __halves2half2(l0, l1);
        }
        uint32_t off = (uint32_t)n * 1024 + ((c ^ (n & 7)) << 4);
        *reinterpret_cast<uint4*>(sm + off)         = *reinterpret_cast<uint4*>(hh);
        *reinterpret_cast<uint4*>(sm + 65536 + off) = *reinterpret_cast<uint4*>(ll);
    }

    // Per-thread output coordinates (mma c-frag layout).
    const int nn  = n0 + wid * 8 + (lane & 3) * 2;
    const int mr0 = m0 + (lane >> 2);
    const int mr1 = mr0 + 8;
    const float bav0 = ba[nn];
    const float bav1 = ba[nn + 1];

    float cc[4];
#pragma unroll
    for (int j = 0; j < 4; j++) cc[j] = 0.f;

    // ldsm row/addr components (loop-invariant).
    const int rA = (lane & 7) + ((lane >> 3) & 1) * 8;      // A row 0..15
    const int rB = wid * 8 + (lane & 7);                    // B row 0..63
    const uint32_t aRow  = sbH  + (uint32_t)rA * 1024;
    const uint32_t bRowH = sbWh + (uint32_t)rB * 1024;
    const uint32_t bRowL = sbWl + (uint32_t)rB * 1024;
    const int swA = rA & 7, swB = rB & 7;

    __syncthreads();

    // Y prefetch for t=0.
    float2 pf[2][4];
    {
        const float* yb = g_Y;
#pragma unroll
        for (int g = 0; g < 4; g++) {
            pf[0][g] = *reinterpret_cast<const float2*>(
                yb + (size_t)mr0 * N4 + g * HID + nn);
            pf[1][g] = *reinterpret_cast<const float2*>(
                yb + (size_t)mr1 * N4 + g * HID + nn);
        }
    }

    for (int t = 0; t < T_LEN; t++) {
        float ac0[4] = {0.f, 0.f, 0.f, 0.f};
        float ac1[4] = {0.f, 0.f, 0.f, 0.f};
        float ac2[4] = {0.f, 0.f, 0.f, 0.f};
        float ac3[4] = {0.f, 0.f, 0.f, 0.f};

        if (t > 0) {
            // Stage h(t-1) fp16 tile from g_h16 buf[(t-1)&1] into Hs.
            const __half* hsrc = g_h16 + (size_t)((t - 1) & 1) * 131072
                                 + (size_t)m0 * HID;
#pragma unroll
            for (int i = 0; i < 4; i++) {
                int idx = tid + i * 256;      // row(0..15) x chunk(0..63)
                int r = idx >> 6;
                int c = idx & 63;
                uint4 v = *reinterpret_cast<const uint4*>(
                    hsrc + (size_t)r * HID + c * 8);
                *reinterpret_cast<uint4*>(
                    sm + 131072 + (uint32_t)r * 1024 + ((c ^ (r & 7)) << 4)) = v;
            }
            __syncthreads();

            // 4 independent accumulator chains (depth 16 each).
#pragma unroll 4
            for (int k0 = 0; k0 < 512; k0 += 32) {
                const int cb = k0 >> 3;
                const int chA = cb + (lane >> 4);
                const int chB = cb + (lane >> 3);
                uint32_t a0[4], a1[4], bh[4], bl[4];
                ldsm_x4(a0[0], a0[1], a0[2], a0[3],
                        aRow + ((chA ^ swA) << 4));
                ldsm_x4(a1[0], a1[1], a1[2], a1[3],
                        aRow + (((chA + 2) ^ swA) << 4));
                ldsm_x4(bh[0], bh[1], bh[2], bh[3],
                        bRowH + ((chB ^ swB) << 4));
                ldsm_x4(bl[0], bl[1], bl[2], bl[3],
                        bRowL + ((chB ^ swB) << 4));
                mma16816(ac0, a0, bh[0], bh[1]);
                mma16816(ac1, a1, bh[2], bh[3]);
                mma16816(ac2, a0, bl[0], bl[1]);
                mma16816(ac3, a1, bl[2], bl[3]);
            }
            __syncthreads();   // Hs reusable next step
        }

        // Gates + state update (c in regs).
        float acc[4];
#pragma unroll
        for (int j = 0; j < 4; j++)
            acc[j] = (ac0[j] + ac2[j]) + (ac1[j] + ac3[j]);

        float hv[4];
#pragma unroll
        for (int r = 0; r < 2; r++) {
            float a0 = acc[r * 2 + 0] + bav0;
            float a1 = acc[r * 2 + 1] + bav1;
            float f0 = sigf(pf[r][0].x + a0), f1 = sigf(pf[r][0].y + a1);
            float i0 = sigf(pf[r][1].x + a0), i1 = sigf(pf[r][1].y + a1);
            float o0 = sigf(pf[r][2].x + a0), o1 = sigf(pf[r][2].y + a1);
            float g0 = tanh_fast(pf[r][3].x + a0);
            float g1 = tanh_fast(pf[r][3].y + a1);
            cc[r * 2 + 0] = f0 * cc[r * 2 + 0] + i0 * g0;
            cc[r * 2 + 1] = f1 * cc[r * 2 + 1] + i1 * g1;
            hv[r * 2 + 0] = o0 * tanh_fast(cc[r * 2 + 0]);
            hv[r * 2 + 1] = o1 * tanh_fast(cc[r * 2 + 1]);
        }

        // Store h: fp32 to out, fp16 to g_h16 buf[t&1].
        {
            float* ob = out + ((size_t)t * BSZ) * HID;
            *reinterpret_cast<float2*>(ob + (size_t)mr0 * HID + nn) =
                make_float2(hv[0], hv[1]);
            *reinterpret_cast<float2*>(ob + (size_t)mr1 * HID + nn) =
                make_float2(hv[2], hv[3]);
            __half* hb = g_h16 + (size_t)(t & 1) * 131072;
            *reinterpret_cast<__half2*>(hb + (size_t)mr0 * HID + nn) =
                __floats2half2_rn(hv[0], hv[1]);
            *reinterpret_cast<__half2*>(hb + (size_t)mr1 * HID + nn) =
                __floats2half2_rn(hv[2], hv[3]);
            if (hn && t == T_LEN - 1) {
                *reinterpret_cast<float2*>(hn + (size_t)mr0 * HID + nn) =
                    make_float2(hv[0], hv[1]);
                *reinterpret_cast<float2*>(hn + (size_t)mr1 * HID + nn) =
                    make_float2(hv[2], hv[3]);
            }
        }

        if (t < T_LEN - 1) {
            // Prefetch Y for t+1 (independent of h; hidden under barrier).
            const float* yb = g_Y + (size_t)(t + 1) * BSZ * N4;
#pragma unroll
            for (int g = 0; g < 4; g++) {
                pf[0][g] = *reinterpret_cast<const float2*>(
                    yb + (size_t)mr0 * N4 + g * HID + nn);
                pf[1][g] = *reinterpret_cast<const float2*>(
                    yb + (size_t)mr1 * N4 + g * HID + nn);
            }

            // Cluster barrier: release h(t) stores, acquire peers' stores.
            CLUSTER_ARRIVE();
            CLUSTER_WAIT();
        }
    }
}

// ---------------------------------------------------------------------------
extern "C" void kernel_launch(void* const* d_in, const int* in_sizes, int n_in,
                              void* d_out, int out_size)
{
    (void)in_sizes; (void)n_in;
    const float* X   = (const float*)d_in[0];
    const float* Wf  = (const float*)d_in[1];
    const float* Wi  = (const float*)d_in[2];
    const float* Wo  = (const float*)d_in[3];
    const float* Wa  = (const float*)d_in[4];
    const float* Waa = (const float*)d_in[5];
    const float* bf  = (const float*)d_in[6];
    const float* bi  = (const float*)d_in[7];
    const float* bo  = (const float*)d_in[8];
    const float* ba  = (const float*)d_in[9];
    float* out = (float*)d_out;

    const int gemm_smem = 65536;    // 64 KB
    const int rec_smem  = 147456;   // 64+64+16 KB
    static bool attr_set = false;
    if (!attr_set) {
        cudaFuncSetAttribute(gemm_xproj_mma,
                             cudaFuncAttributeMaxDynamicSharedMemorySize,
                             gemm_smem);
        cudaFuncSetAttribute(lstm_persistent_tc,
                             cudaFuncAttributeMaxDynamicSharedMemorySize,
                             rec_smem);
        attr_set = true;
    }

    convert_x_h<<<65536, 256>>>(X);
    convert_w_h<<<1024, 256>>>(Wf, Wi, Wo, Wa);

    dim3 g1(16, 1024);
    gemm_xproj_mma<<<g1, 256, gemm_smem>>>(bf, bi, bo);

    const size_t step_elems = (size_t)BSZ * HID;
    const size_t outs_elems = (size_t)T_LEN * step_elems;
    float* hn_ptr = ((size_t)out_size >= outs_elems + step_elems)
                        ? out + outs_elems : nullptr;

    lstm_persistent_tc<<<128, 256, rec_smem>>>(Waa, ba, out, hn_ptr);
}

// round 11
// speedup vs baseline: 1.3683x; 1.3683x over previous
#include <cuda_runtime.h>
#include <cuda_fp16.h>
#include <math.h>
#include <cstdint>

#define T_LEN 512
#define BSZ   256
#define DIM   512
#define HID   512
#define N4    (4 * HID)       /* 2048 */

// Scratch: input projections [T][B][4H].
__device__ float g_Y[268435456];          // 131072 * 2048
// fp16 copies of X and W (W rows: gate*512 + r, gates f,i,o,a).
__device__ __half g_Xf[67108864];         // 131072 * 512
__device__ __half g_Wf[1048576];          // 2048 * 512
// Double-buffered fp16 h state [2][256][512].
__device__ __half g_h16[262144];
// Per-mTile-group barrier state: group g uses [g*64] = count, [g*64+32] = gen.
__device__ unsigned g_sync2[1024];

// ============================================================================
// helpers
// ============================================================================
__device__ __forceinline__ uint32_t smem_u32(const void* p) {
    uint32_t a;
    asm("{ .reg .u64 t; cvta.to.shared.u64 t, %1; cvt.u32.u64 %0, t; }"
        : "=r"(a) : "l"(p));
    return a;
}
__device__ __forceinline__ void ldsm_x4(uint32_t& r0, uint32_t& r1,
                                        uint32_t& r2, uint32_t& r3,
                                        uint32_t addr) {
    asm volatile("ldmatrix.sync.aligned.m8n8.x4.shared.b16 {%0,%1,%2,%3}, [%4];"
                 : "=r"(r0), "=r"(r1), "=r"(r2), "=r"(r3) : "r"(addr));
}
__device__ __forceinline__ void mma16816(float* c, const uint32_t* a,
                                         uint32_t b0, uint32_t b1) {
    asm volatile(
        "mma.sync.aligned.m16n8k16.row.col.f32.f16.f16.f32 "
        "{%0,%1,%2,%3}, {%4,%5,%6,%7}, {%8,%9}, {%0,%1,%2,%3};"
        : "+f"(c[0]), "+f"(c[1]), "+f"(c[2]), "+f"(c[3])
        : "r"(a[0]), "r"(a[1]), "r"(a[2]), "r"(a[3]), "r"(b0), "r"(b1));
}
#define CP_ASYNC16(dst, src) \
    asm volatile("cp.async.cg.shared.global [%0], [%1], 16;" \
                 :: "r"(dst), "l"(src) : "memory")
#define CP_COMMIT() asm volatile("cp.async.commit_group;" ::: "memory")
#define CP_WAIT(n)  asm volatile("cp.async.wait_group %0;" :: "n"(n) : "memory")

// ============================================================================
// One-time fp32 -> fp16 conversion kernels.
// ============================================================================
__global__ __launch_bounds__(256) void convert_x_h(const float* __restrict__ X) {
    size_t i = (size_t)blockIdx.x * blockDim.x + threadIdx.x;   // per float4
    float4 v = reinterpret_cast<const float4*>(X)[i];
    __half2 a = __floats2half2_rn(v.x, v.y);
    __half2 b = __floats2half2_rn(v.z, v.w);
    reinterpret_cast<uint2*>(g_Xf)[i] =
        make_uint2(*reinterpret_cast<uint32_t*>(&a),
                   *reinterpret_cast<uint32_t*>(&b));
}
__global__ __launch_bounds__(256) void convert_w_h(
    const float* __restrict__ Wf, const float* __restrict__ Wi,
    const float* __restrict__ Wo, const float* __restrict__ Wa) {
    size_t i = (size_t)blockIdx.x * blockDim.x + threadIdx.x;   // per float4
    int gate = (int)(i >> 16);                  // 65536 float4 per gate
    const float* W = (gate == 0) ? Wf : (gate == 1) ? Wi : (gate == 2) ? Wo : Wa;
    float4 v = reinterpret_cast<const float4*>(W)[i & 65535];
    __half2 a = __floats2half2_rn(v.x, v.y);
    __half2 b = __floats2half2_rn(v.z, v.w);
    reinterpret_cast<uint2*>(g_Wf)[i] =
        make_uint2(*reinterpret_cast<uint32_t*>(&a),
                   *reinterpret_cast<uint32_t*>(&b));
}

// ============================================================================
// GEMM1 via fp16 mma.sync (1 term, fp32 acc), cp.async 2-stage pipeline.
// (round-8 version, verbatim)
// ============================================================================
__global__ __launch_bounds__(256, 2) void gemm_xproj_mma(
    const float* __restrict__ bf, const float* __restrict__ bi,
    const float* __restrict__ bo)
{
    extern __shared__ __align__(128) char smem[];
    const uint32_t sb = smem_u32(smem);

    const int tid  = threadIdx.x;
    const int lane = tid & 31;
    const int wid  = tid >> 5;
    const int wm   = wid >> 1;
    const int wn   = wid & 1;

    const int nTile = blockIdx.x;
    const int mBase = blockIdx.y * 128;
    const int gate  = nTile >> 2;
    const int rowG  = (nTile & 3) * 128;
    const float* bias = (gate == 0) ? bf : (gate == 1) ? bi : (gate == 2) ? bo : nullptr;

    const __half* A = g_Xf + (size_t)mBase * DIM;
    const __half* B = g_Wf + (size_t)nTile * 128 * DIM;

    float c[2][8][4];
#pragma unroll
    for (int mf = 0; mf < 2; mf++)
#pragma unroll
        for (int nf = 0; nf < 8; nf++)
#pragma unroll
            for (int q = 0; q < 4; q++) c[mf][nf][q] = 0.f;

    auto stage = [&](int chunk, int s) {
        const int kb = chunk * 64;
        const uint32_t sOff = (uint32_t)s * 32768;
#pragma unroll
        for (int it = 0; it < 4; it++) {
            int idx = tid + it * 256;
            int row = idx >> 3;
            int ch  = idx & 7;
            uint32_t off = sOff + (uint32_t)row * 128 + ((ch ^ (row & 7)) << 4);
            const size_t g = (size_t)row * DIM + kb + ch * 8;
            CP_ASYNC16(sb + off,         A + g);
            CP_ASYNC16(sb + off + 16384, B + g);
        }
        CP_COMMIT();
    };

    stage(0, 0);

    for (int chunk = 0; chunk < 8; chunk++) {
        if (chunk < 7) {
            stage(chunk + 1, (chunk + 1) & 1);
            CP_WAIT(1);
        } else {
            CP_WAIT(0);
        }
        __syncthreads();

        const uint32_t sOff = (uint32_t)(chunk & 1) * 32768;
        const uint32_t AS = sOff, BS = sOff + 16384;

#pragma unroll
        for (int ks = 0; ks < 4; ks++) {
            const int chv = ks * 2 + (lane >> 4);

            uint32_t a[2][4];
#pragma unroll
            for (int mf = 0; mf < 2; mf++) {
                const int row = wm * 32 + mf * 16 + (lane & 15);
                const uint32_t addr =
                    sb + AS + (uint32_t)row * 128 + (((chv ^ (row & 7))) << 4);
                ldsm_x4(a[mf][0], a[mf][1], a[mf][2], a[mf][3], addr);
            }
            uint32_t b[4][4];
#pragma unroll
            for (int np = 0; np < 4; np++) {
                const int row = wn * 64 + np * 16 + (lane & 15);
                const uint32_t addr =
                    sb + BS + (uint32_t)row * 128 + (((chv ^ (row & 7))) << 4);
                ldsm_x4(b[np][0], b[np][1], b[np][2], b[np][3], addr);
            }
#pragma unroll
            for (int mf = 0; mf < 2; mf++)
#pragma unroll
                for (int nf = 0; nf < 8; nf++) {
                    const int np = nf >> 1, s = nf & 1;
                    mma16816(c[mf][nf], a[mf], b[np][s], b[np][s + 2]);
                }
        }
        __syncthreads();
    }

    const int colBase = nTile * 128 + wn * 64 + (lane & 3) * 2;
    const int rBase   = mBase + wm * 32 + (lane >> 2);
#pragma unroll
    for (int nf = 0; nf < 8; nf++) {
        const int col = colBase + nf * 8;
        const int ln  = wn * 64 + nf * 8 + (lane & 3) * 2;
        float b0 = bias ? __ldg(bias + rowG + ln)     : 0.f;
        float b1 = bias ? __ldg(bias + rowG + ln + 1) : 0.f;
#pragma unroll
        for (int mf = 0; mf < 2; mf++) {
            const size_t r0 = (size_t)(rBase + mf * 16);
            float2 o0 = make_float2(c[mf][nf][0] + b0, c[mf][nf][1] + b1);
            float2 o1 = make_float2(c[mf][nf][2] + b0, c[mf][nf][3] + b1);
            *reinterpret_cast<float2*>(g_Y + r0 * N4 + col)       = o0;
            *reinterpret_cast<float2*>(g_Y + (r0 + 8) * N4 + col) = o1;
        }
    }
}

// ============================================================================
// Persistent tensor-core recurrence.
// 128 blocks = 16 groups (mTile, 16 rows) x 8 (nTile, 64 cols), 256 threads.
// The 16 mTile groups are fully independent recurrences; each group uses its
// own 8-CTA software barrier. W_aa as single fp16 term; 2 accumulator chains.
// smem: W[64][512]f16 (64KB) | Hs[16][512]f16 (16KB). c in registers.
// ============================================================================
__device__ __forceinline__ float sigf(float x) {
    return 1.f / (1.f + __expf(-x));
}
__device__ __forceinline__ float tanh_fast(float x) {
    return 2.f / (1.f + __expf(-2.f * x)) - 1.f;
}

__global__ __launch_bounds__(256, 1) void lstm_persistent_tc(
    const float* __restrict__ Waa,
    const float* __restrict__ ba,
    float*       __restrict__ out,
    float*       __restrict__ hn)
{
    extern __shared__ __align__(128) char sm[];
    const uint32_t sb  = smem_u32(sm);
    const uint32_t sbW = sb;
    const uint32_t sbH = sb + 65536;

    const int tid  = threadIdx.x;
    const int lane = tid & 31;
    const int wid  = tid >> 5;                 // 0..7: n-subtile
    const int grp  = blockIdx.x >> 3;          // mTile group 0..15
    const int m0   = grp * 16;                 // batch rows
    const int n0   = (blockIdx.x & 7) * 64;    // hidden cols

    // --- one-time: Waa[n0+n][k] -> smem fp16, swizzled 16B chunks ---
#pragma unroll
    for (int i = 0; i < 16; i++) {
        int idx = tid + i * 256;          // n(0..63) x chunk(0..63)
        int n = idx >> 6;
        int c = idx & 63;
        const float* src = Waa + (size_t)(n0 + n) * HID + c * 8;
        float4 v0 = *reinterpret_cast<const float4*>(src);
        float4 v1 = *reinterpret_cast<const float4*>(src + 4);
        __half2 hh[4];
        hh[0] = __floats2half2_rn(v0.x, v0.y);
        hh[1] = __floats2half2_rn(v0.z, v0.w);
        hh[2] = __floats2half2_rn(v1.x, v1.y);
        hh[3] = __floats2half2_rn(v1.z, v1.w);
        uint32_t off = (uint32_t)n * 1024 + ((c ^ (n & 7)) << 4);
        *reinterpret_cast<uint4*>(sm + off) = *reinterpret_cast<uint4*>(hh);
    }

    // Per-thread output coordinates (mma c-frag layout).
    const int nn  = n0 + wid * 8 + (lane & 3) * 2;
    const int mr0 = m0 + (lane >> 2);
    const int mr1 = mr0 + 8;
    const float bav0 = ba[nn];
    const float bav1 = ba[nn + 1];

    float cc[4];
#pragma unroll
    for (int j = 0; j < 4; j++) cc[j] = 0.f;

    // ldsm row/addr components (loop-invariant).
    const int rA = (lane & 7) + ((lane >> 3) & 1) * 8;      // A row 0..15
    const int rB = wid * 8 + (lane & 7);                    // B row 0..63
    const uint32_t aRow = sbH + (uint32_t)rA * 1024;
    const uint32_t bRow = sbW + (uint32_t)rB * 1024;
    const int swA = rA & 7, swB = rB & 7;

    __syncthreads();

    // Per-group barrier pointers.
    volatile unsigned* genp = &g_sync2[grp * 64 + 32];
    unsigned* cntp = &g_sync2[grp * 64];

    // Y prefetch for t=0.
    float2 pf[2][4];
    {
        const float* yb = g_Y;
#pragma unroll
        for (int g = 0; g < 4; g++) {
            pf[0][g] = *reinterpret_cast<const float2*>(
                yb + (size_t)mr0 * N4 + g * HID + nn);
            pf[1][g] = *reinterpret_cast<const float2*>(
                yb + (size_t)mr1 * N4 + g * HID + nn);
        }
    }

    for (int t = 0; t < T_LEN; t++) {
        float ac0[4] = {0.f, 0.f, 0.f, 0.f};
        float ac1[4] = {0.f, 0.f, 0.f, 0.f};

        if (t > 0) {
            // Stage h(t-1) fp16 tile from g_h16 buf[(t-1)&1] into Hs.
            const __half* hsrc = g_h16 + (size_t)((t - 1) & 1) * 131072
                                 + (size_t)m0 * HID;
#pragma unroll
            for (int i = 0; i < 4; i++) {
                int idx = tid + i * 256;      // row(0..15) x chunk(0..63)
                int r = idx >> 6;
                int c = idx & 63;
                uint4 v = *reinterpret_cast<const uint4*>(
                    hsrc + (size_t)r * HID + c * 8);
                *reinterpret_cast<uint4*>(
                    sm + 65536 + (uint32_t)r * 1024 + ((c ^ (r & 7)) << 4)) = v;
            }
            __syncthreads();

            // Single-term fp16 MMA, 2 independent accumulator chains.
#pragma unroll 4
            for (int k0 = 0; k0 < 512; k0 += 32) {
                const int cb = k0 >> 3;
                const int chA = cb + (lane >> 4);
                const int chB = cb + (lane >> 3);
                uint32_t a0[4], a1[4], b[4];
                ldsm_x4(a0[0], a0[1], a0[2], a0[3],
                        aRow + ((chA ^ swA) << 4));
                ldsm_x4(a1[0], a1[1], a1[2], a1[3],
                        aRow + (((chA + 2) ^ swA) << 4));
                ldsm_x4(b[0], b[1], b[2], b[3],
                        bRow + ((chB ^ swB) << 4));
                mma16816(ac0, a0, b[0], b[1]);
                mma16816(ac1, a1, b[2], b[3]);
            }
            __syncthreads();   // Hs reusable next step
        }

        // Gates + state update (c in regs).
        float acc[4];
#pragma unroll
        for (int j = 0; j < 4; j++) acc[j] = ac0[j] + ac1[j];

        float hv[4];
#pragma unroll
        for (int r = 0; r < 2; r++) {
            float a0 = acc[r * 2 + 0] + bav0;
            float a1 = acc[r * 2 + 1] + bav1;
            float f0 = sigf(pf[r][0].x + a0), f1 = sigf(pf[r][0].y + a1);
            float i0 = sigf(pf[r][1].x + a0), i1 = sigf(pf[r][1].y + a1);
            float o0 = sigf(pf[r][2].x + a0), o1 = sigf(pf[r][2].y + a1);
            float g0 = tanh_fast(pf[r][3].x + a0);
            float g1 = tanh_fast(pf[r][3].y + a1);
            cc[r * 2 + 0] = f0 * cc[r * 2 + 0] + i0 * g0;
            cc[r * 2 + 1] = f1 * cc[r * 2 + 1] + i1 * g1;
            hv[r * 2 + 0] = o0 * tanh_fast(cc[r * 2 + 0]);
            hv[r * 2 + 1] = o1 * tanh_fast(cc[r * 2 + 1]);
        }

        // Store h: fp32 to out, fp16 to g_h16 buf[t&1].
        {
            float* ob = out + ((size_t)t * BSZ) * HID;
            *reinterpret_cast<float2*>(ob + (size_t)mr0 * HID + nn) =
                make_float2(hv[0], hv[1]);
            *reinterpret_cast<float2*>(ob + (size_t)mr1 * HID + nn) =
                make_float2(hv[2], hv[3]);
            __half* hb = g_h16 + (size_t)(t & 1) * 131072;
            *reinterpret_cast<__half2*>(hb + (size_t)mr0 * HID + nn) =
                __floats2half2_rn(hv[0], hv[1]);
            *reinterpret_cast<__half2*>(hb + (size_t)mr1 * HID + nn) =
                __floats2half2_rn(hv[2], hv[3]);
            if (hn && t == T_LEN - 1) {
                *reinterpret_cast<float2*>(hn + (size_t)mr0 * HID + nn) =
                    make_float2(hv[0], hv[1]);
                *reinterpret_cast<float2*>(hn + (size_t)mr1 * HID + nn) =
                    make_float2(hv[2], hv[3]);
            }
        }

        if (t < T_LEN - 1) {
            // Prefetch Y for t+1 (independent of h; hidden under barrier).
            const float* yb = g_Y + (size_t)(t + 1) * BSZ * N4;
#pragma unroll
            for (int g = 0; g < 4; g++) {
                pf[0][g] = *reinterpret_cast<const float2*>(
                    yb + (size_t)mr0 * N4 + g * HID + nn);
                pf[1][g] = *reinterpret_cast<const float2*>(
                    yb + (size_t)mr1 * N4 + g * HID + nn);
            }

            // Per-group (8-CTA) barrier.
            __syncthreads();
            if (tid == 0) {
                unsigned gen = *genp;
                __threadfence();
                if (atomicAdd(cntp, 1u) == 7u) {
                    atomicExch(cntp, 0u);
                    __threadfence();
                    *genp = gen + 1;
                } else {
                    while (*genp == gen) { }
                }
                __threadfence();
            }
            __syncthreads();
        }
    }
}

// ---------------------------------------------------------------------------
extern "C" void kernel_launch(void* const* d_in, const int* in_sizes, int n_in,
                              void* d_out, int out_size)
{
    (void)in_sizes; (void)n_in;
    const float* X   = (const float*)d_in[0];
    const float* Wf  = (const float*)d_in[1];
    const float* Wi  = (const float*)d_in[2];
    const float* Wo  = (const float*)d_in[3];
    const float* Wa  = (const float*)d_in[4];
    const float* Waa = (const float*)d_in[5];
    const float* bf  = (const float*)d_in[6];
    const float* bi  = (const float*)d_in[7];
    const float* bo  = (const float*)d_in[8];
    const float* ba  = (const float*)d_in[9];
    float* out = (float*)d_out;

    const int gemm_smem = 65536;    // 64 KB
    const int rec_smem  = 81920;    // 64 + 16 KB
    static bool attr_set = false;
    if (!attr_set) {
        cudaFuncSetAttribute(gemm_xproj_mma,
                             cudaFuncAttributeMaxDynamicSharedMemorySize,
                             gemm_smem);
        cudaFuncSetAttribute(lstm_persistent_tc,
                             cudaFuncAttributeMaxDynamicSharedMemorySize,
                             rec_smem);
        attr_set = true;
    }

    convert_x_h<<<65536, 256>>>(X);
    convert_w_h<<<1024, 256>>>(Wf, Wi, Wo, Wa);

    dim3 g1(16, 1024);
    gemm_xproj_mma<<<g1, 256, gemm_smem>>>(bf, bi, bo);

    const size_t step_elems = (size_t)BSZ * HID;
    const size_t outs_elems = (size_t)T_LEN * step_elems;
    float* hn_ptr = ((size_t)out_size >= outs_elems + step_elems)
                        ? out + outs_elems : nullptr;

    lstm_persistent_tc<<<128, 256, rec_smem>>>(Waa, ba, out, hn_ptr);
}